// round 1
// baseline (speedup 1.0000x reference)
#include <cuda_runtime.h>

// VIN-style kernel, fully fused:
//  r   = conv3x3(X, W_eff) + b_eff          (150-ch hidden layer collapsed)
//  qr  = conv3x3(r, q_w)   [10 maps, iteration-invariant]
//  v0  = max_l qr[l]
//  39x: v = max_l ( qr[l] + conv3x3(v, w[l]) )
// One CTA per batch image; everything resident in SMEM.

#define THREADS   256
#define HH        64
#define WW        64
#define NPX       4096          // 64*64
#define LQ        10
#define LH        150
#define VW        72            // padded row stride (floats): 4 + 64 + 4
#define VH        66            // padded rows: 1 + 64 + 1
#define XPAD      4             // interior starts at col 4
#define SMEM_BYTES ((LQ * NPX + 2 * VH * VW) * (int)sizeof(float))

__global__ void __launch_bounds__(THREADS, 1)
vin_kernel(const float* __restrict__ X, const float* __restrict__ h_w,
           const float* __restrict__ h_b, const float* __restrict__ r_w,
           const float* __restrict__ q_w, const float* __restrict__ ww,
           const int* __restrict__ kptr, float* __restrict__ out)
{
    extern __shared__ float smem[];
    float* qr   = smem;                 // LQ * NPX
    float* vbuf = qr + LQ * NPX;        // VH * VW, zero-padded border
    float* rbuf = vbuf + VH * VW;       // VH * VW, zero-padded border
    __shared__ float s_weff[19];        // [0:18) = W_eff (2x3x3), [18] = b_eff
    __shared__ float s_qw[LQ * 9];
    __shared__ float s_w[LQ * 9];

    const int tid = threadIdx.x;
    const int b   = blockIdx.x;
    const float* Xb = X + (size_t)b * 2 * NPX;

    // ---- collapse hidden layer into W_eff / b_eff; stage filter taps ----
    if (tid < LQ * 9) { s_qw[tid] = q_w[tid]; s_w[tid] = ww[tid]; }
    if (tid < 19) {
        float acc = 0.f;
        if (tid < 18) {
            for (int l = 0; l < LH; ++l) acc += r_w[l] * h_w[l * 18 + tid];
        } else {
            for (int l = 0; l < LH; ++l) acc += r_w[l] * h_b[l];
        }
        s_weff[tid] = acc;
    }
    for (int i = tid; i < VH * VW; i += THREADS) { vbuf[i] = 0.f; rbuf[i] = 0.f; }
    __syncthreads();

    // ---- r = conv3x3(X, W_eff) + b_eff (SAME, zero pad) ----
    for (int px = tid; px < NPX; px += THREADS) {
        int y = px >> 6, x = px & 63;
        float acc = s_weff[18];
        #pragma unroll
        for (int c = 0; c < 2; ++c)
            #pragma unroll
            for (int ky = 0; ky < 3; ++ky) {
                int iy = y - 1 + ky;
                if (iy < 0 || iy >= HH) continue;
                #pragma unroll
                for (int kx = 0; kx < 3; ++kx) {
                    int ix = x - 1 + kx;
                    if (ix < 0 || ix >= WW) continue;
                    acc += s_weff[c * 9 + ky * 3 + kx] * Xb[c * NPX + iy * WW + ix];
                }
            }
        rbuf[(y + 1) * VW + x + XPAD] = acc;
    }
    __syncthreads();

    // ---- qr[l] = conv3x3(r, q_w[l]);  v0 = max_l qr[l] ----
    for (int px = tid; px < NPX; px += THREADS) {
        int y = px >> 6, x = px & 63;
        float n[9];
        #pragma unroll
        for (int ky = 0; ky < 3; ++ky)
            #pragma unroll
            for (int kx = 0; kx < 3; ++kx)
                n[ky * 3 + kx] = rbuf[(y + ky) * VW + (x + XPAD - 1 + kx)];
        float vmax = -1e30f;
        #pragma unroll
        for (int l = 0; l < LQ; ++l) {
            float s = 0.f;
            #pragma unroll
            for (int t = 0; t < 9; ++t) s += s_qw[l * 9 + t] * n[t];
            qr[l * NPX + px] = s;
            vmax = fmaxf(vmax, s);
        }
        vbuf[(y + 1) * VW + x + XPAD] = vmax;
    }
    __syncthreads();

    // ---- hoist the 90 loop taps into registers ----
    float wt[LQ * 9];
    #pragma unroll
    for (int i = 0; i < LQ * 9; ++i) wt[i] = s_w[i];

    const int k = kptr[0];

    // ---- value iteration: v = max_l(qr[l] + conv3x3(v, w[l])) ----
    for (int it = 0; it < k - 1; ++it) {
        float res[4][4];
        #pragma unroll
        for (int s = 0; s < 4; ++s) {
            int strip = s * THREADS + tid;        // 0..1023, 4-px horizontal strip
            int y  = strip >> 4;                  // 0..63
            int x0 = (strip & 15) << 2;           // 0,4,...,60
            // neighborhood: padded rows y..y+2, padded cols x0+3..x0+8
            float n[3][6];
            #pragma unroll
            for (int r = 0; r < 3; ++r) {
                const float* rowp = vbuf + (y + r) * VW;
                float4 a = *(const float4*)(rowp + x0 + 4);     // aligned
                n[r][0] = rowp[x0 + 3];
                n[r][1] = a.x; n[r][2] = a.y; n[r][3] = a.z; n[r][4] = a.w;
                n[r][5] = rowp[x0 + 8];
            }
            float vm0 = -1e30f, vm1 = -1e30f, vm2 = -1e30f, vm3 = -1e30f;
            #pragma unroll
            for (int l = 0; l < LQ; ++l) {
                float4 q4 = *(const float4*)(qr + l * NPX + y * WW + x0);
                float a0 = q4.x, a1 = q4.y, a2 = q4.z, a3 = q4.w;
                #pragma unroll
                for (int ky = 0; ky < 3; ++ky)
                    #pragma unroll
                    for (int kx = 0; kx < 3; ++kx) {
                        float c = wt[l * 9 + ky * 3 + kx];
                        a0 += c * n[ky][0 + kx];
                        a1 += c * n[ky][1 + kx];
                        a2 += c * n[ky][2 + kx];
                        a3 += c * n[ky][3 + kx];
                    }
                vm0 = fmaxf(vm0, a0); vm1 = fmaxf(vm1, a1);
                vm2 = fmaxf(vm2, a2); vm3 = fmaxf(vm3, a3);
            }
            res[s][0] = vm0; res[s][1] = vm1; res[s][2] = vm2; res[s][3] = vm3;
        }
        __syncthreads();   // all reads of old v done
        #pragma unroll
        for (int s = 0; s < 4; ++s) {
            int strip = s * THREADS + tid;
            int y  = strip >> 4;
            int x0 = (strip & 15) << 2;
            *(float4*)(vbuf + (y + 1) * VW + x0 + 4) =
                make_float4(res[s][0], res[s][1], res[s][2], res[s][3]);
        }
        __syncthreads();   // new v visible
    }

    // ---- write v out: [B,1,64,64] ----
    for (int px = tid; px < NPX; px += THREADS) {
        int y = px >> 6, x = px & 63;
        out[(size_t)b * NPX + px] = vbuf[(y + 1) * VW + x + XPAD];
    }
}

extern "C" void kernel_launch(void* const* d_in, const int* in_sizes, int n_in,
                              void* d_out, int out_size) {
    const float* X   = (const float*)d_in[0];
    const float* h_w = (const float*)d_in[1];
    const float* h_b = (const float*)d_in[2];
    const float* r_w = (const float*)d_in[3];
    const float* q_w = (const float*)d_in[4];
    const float* w_  = (const float*)d_in[5];
    const int*   k   = (const int*)d_in[6];

    int B = in_sizes[0] / (2 * NPX);   // 128

    cudaFuncSetAttribute(vin_kernel,
                         cudaFuncAttributeMaxDynamicSharedMemorySize, SMEM_BYTES);
    vin_kernel<<<B, THREADS, SMEM_BYTES>>>(X, h_w, h_b, r_w, q_w, w_, k,
                                           (float*)d_out);
}